// round 1
// baseline (speedup 1.0000x reference)
#include <cuda_runtime.h>
#include <cstdint>

// ---------------------------------------------------------------------------
// SPNet: palette CNN (pruned to the 4x4 corner actually used) + per-pixel
// argmax-gather over 16 palette classes.
//
// Shapes: x [16,3,400,400], b_logits [16,16,400,400], out [16,3,400,400]
// Palette branch receptive-field pruning:
//   pal needs c[:,:, :4,:4] -> h5[0:4]^2 -> h4[0:8]^2 -> h3[0:16]^2
//   -> h2[0:32]^2 -> h1[0:64]^2 -> x[0:128]^2
// ---------------------------------------------------------------------------

#define BATCH 16
#define HW    160000          // 400*400
#define HW4   40000           // float4 per image plane

// scratch (static __device__ globals: no allocation at runtime)
__device__ float g_h1[BATCH * 6  * 64 * 64];   // conv1 out (leaky)
__device__ float g_h2[BATCH * 12 * 32 * 32];   // conv2 out (leaky)
__device__ float g_pal[BATCH * 3 * 16];        // palette colors

__device__ __forceinline__ float leaky(float v) {
    return (v >= 0.f) ? v : 0.01f * v;
}

// ---------------------------------------------------------------------------
// conv1: x[b, 0:3, (-1..127), (-1..127)] -> h1[b, 0:6, 0:64, 0:64]
// stride 2, pad 1, 3x3. grid (4 strips, 16 batch), 256 threads.
// thread = (j in 0..63, rowgroup in 0..3 each 4 rows)
// ---------------------------------------------------------------------------
__global__ void conv1_kernel(const float* __restrict__ x,
                             const float* __restrict__ w1,
                             const float* __restrict__ b1) {
    const int b   = blockIdx.y;
    const int s   = blockIdx.x;          // 0..3 (16-row output strips)
    const int tid = threadIdx.x;         // 256
    const int j   = tid & 63;
    const int rg  = tid >> 6;            // 0..3
    const int ibase = s * 16 + rg * 4;

    __shared__ float sw[162];
    __shared__ float sb[6];
    if (tid < 162) sw[tid] = w1[tid];
    if (tid < 6)   sb[tid] = b1[tid];
    __syncthreads();

    float acc[6][4];
#pragma unroll
    for (int oc = 0; oc < 6; oc++)
#pragma unroll
        for (int r = 0; r < 4; r++) acc[oc][r] = 0.f;

#pragma unroll
    for (int ic = 0; ic < 3; ic++) {
        const float* xp = x + (size_t)(b * 3 + ic) * HW;
#pragma unroll
        for (int di = 0; di < 3; di++) {
#pragma unroll
            for (int dj = 0; dj < 3; dj++) {
                const int xj = 2 * j + dj - 1;        // -1 .. 127 (<400)
                float wv[6];
#pragma unroll
                for (int oc = 0; oc < 6; oc++)
                    wv[oc] = sw[oc * 27 + ic * 9 + di * 3 + dj];
#pragma unroll
                for (int r = 0; r < 4; r++) {
                    const int yi = 2 * (ibase + r) + di - 1;  // -1 .. 127
                    float v = 0.f;
                    if (yi >= 0 && xj >= 0) v = xp[yi * 400 + xj];
#pragma unroll
                    for (int oc = 0; oc < 6; oc++)
                        acc[oc][r] = fmaf(wv[oc], v, acc[oc][r]);
                }
            }
        }
    }

#pragma unroll
    for (int oc = 0; oc < 6; oc++)
#pragma unroll
        for (int r = 0; r < 4; r++) {
            float v = leaky(acc[oc][r] + sb[oc]);
            g_h1[((b * 6 + oc) * 64 + ibase + r) * 64 + j] = v;
        }
}

// ---------------------------------------------------------------------------
// conv2: h1[b, 0:6, (-1..63), (-1..63)] -> h2[b, 0:12, 0:32, 0:32]
// grid (4 strips of 8 rows, 16 batch), 128 threads.
// thread = (j in 0..31, rowpair in 0..3 each 2 rows), 12 oc per thread.
// ---------------------------------------------------------------------------
__global__ void conv2_kernel(const float* __restrict__ w2,
                             const float* __restrict__ b2) {
    const int b   = blockIdx.y;
    const int s   = blockIdx.x;          // 0..3
    const int tid = threadIdx.x;         // 128
    const int j   = tid & 31;
    const int rp  = tid >> 5;            // 0..3
    const int i0  = s * 8 + rp * 2;

    __shared__ float sw[648];
    __shared__ float sb[12];
    for (int idx = tid; idx < 648; idx += 128) sw[idx] = w2[idx];
    if (tid < 12) sb[tid] = b2[tid];
    __syncthreads();

    float acc[12][2];
#pragma unroll
    for (int oc = 0; oc < 12; oc++) { acc[oc][0] = 0.f; acc[oc][1] = 0.f; }

    const float* h1b = g_h1 + (size_t)b * 6 * 64 * 64;

#pragma unroll
    for (int ic = 0; ic < 6; ic++) {
#pragma unroll
        for (int di = 0; di < 3; di++) {
#pragma unroll
            for (int dj = 0; dj < 3; dj++) {
                const int yj = 2 * j + dj - 1;       // -1 .. 63
#pragma unroll
                for (int r = 0; r < 2; r++) {
                    const int yi = 2 * (i0 + r) + di - 1;  // -1 .. 63
                    float v = 0.f;
                    if (yi >= 0 && yj >= 0) v = h1b[(ic * 64 + yi) * 64 + yj];
#pragma unroll
                    for (int oc = 0; oc < 12; oc++)
                        acc[oc][r] = fmaf(sw[((oc * 6 + ic) * 3 + di) * 3 + dj],
                                          v, acc[oc][r]);
                }
            }
        }
    }

#pragma unroll
    for (int oc = 0; oc < 12; oc++)
#pragma unroll
        for (int r = 0; r < 2; r++) {
            float v = leaky(acc[oc][r] + sb[oc]);
            g_h2[((b * 12 + oc) * 32 + i0 + r) * 32 + j] = v;
        }
}

// ---------------------------------------------------------------------------
// conv3..6 fused. grid 16 (one block per batch), 256 threads.
// conv3: h2[0:32]^2 -> h3[12,16,16] (smem)
// conv4: h3 -> h4[12,8,8] (smem)
// conv5: h4 -> h5[6,4,4]  (smem)
// conv6: 1x1 -> pal[3,16] (relu) -> g_pal
// ---------------------------------------------------------------------------
__global__ void conv_tail_kernel(const float* __restrict__ w3, const float* __restrict__ b3,
                                 const float* __restrict__ w4, const float* __restrict__ b4,
                                 const float* __restrict__ w5, const float* __restrict__ b5,
                                 const float* __restrict__ w6, const float* __restrict__ b6) {
    const int b   = blockIdx.x;
    const int tid = threadIdx.x;   // 256

    __shared__ float sw3[1296], sw4[1296], sw5[648], sw6[18];
    __shared__ float sb3[12], sb4[12], sb5[6], sb6[3];
    __shared__ float h3[12 * 16 * 16];
    __shared__ float h4[12 * 8 * 8];
    __shared__ float h5[6 * 16];

    for (int idx = tid; idx < 1296; idx += 256) { sw3[idx] = w3[idx]; sw4[idx] = w4[idx]; }
    for (int idx = tid; idx < 648;  idx += 256) sw5[idx] = w5[idx];
    if (tid < 18) sw6[tid] = w6[tid];
    if (tid < 12) { sb3[tid] = b3[tid]; sb4[tid] = b4[tid]; }
    if (tid < 6)  sb5[tid] = b5[tid];
    if (tid < 3)  sb6[tid] = b6[tid];
    __syncthreads();

    // ---- conv3 : 128 threads, (j in 0..15, rowgroup 0..7 each 2 rows), 12 oc
    if (tid < 128) {
        const int j  = tid & 15;
        const int ig = tid >> 4;       // 0..7
        float acc[12][2];
#pragma unroll
        for (int oc = 0; oc < 12; oc++) { acc[oc][0] = sb3[oc]; acc[oc][1] = sb3[oc]; }

        const float* h2b = g_h2 + (size_t)b * 12 * 32 * 32;
        for (int ic = 0; ic < 12; ic++) {
#pragma unroll
            for (int di = 0; di < 3; di++) {
#pragma unroll
                for (int dj = 0; dj < 3; dj++) {
                    const int yj = 2 * j + dj - 1;     // -1..31
#pragma unroll
                    for (int r = 0; r < 2; r++) {
                        const int yi = 2 * (ig * 2 + r) + di - 1;  // -1..31
                        float v = 0.f;
                        if (yi >= 0 && yj >= 0) v = h2b[(ic * 32 + yi) * 32 + yj];
#pragma unroll
                        for (int oc = 0; oc < 12; oc++)
                            acc[oc][r] = fmaf(sw3[((oc * 12 + ic) * 3 + di) * 3 + dj],
                                              v, acc[oc][r]);
                    }
                }
            }
        }
#pragma unroll
        for (int oc = 0; oc < 12; oc++)
#pragma unroll
            for (int r = 0; r < 2; r++)
                h3[(oc * 16 + ig * 2 + r) * 16 + j] = leaky(acc[oc][r]);
    }
    __syncthreads();

    // ---- conv4 : 64 threads, (i in 0..7, j in 0..7), 12 oc
    if (tid < 64) {
        const int j = tid & 7;
        const int i = tid >> 3;
        float acc[12];
#pragma unroll
        for (int oc = 0; oc < 12; oc++) acc[oc] = sb4[oc];

        for (int ic = 0; ic < 12; ic++) {
#pragma unroll
            for (int di = 0; di < 3; di++) {
#pragma unroll
                for (int dj = 0; dj < 3; dj++) {
                    const int yi = 2 * i + di - 1;     // -1..15
                    const int yj = 2 * j + dj - 1;     // -1..15
                    float v = 0.f;
                    if (yi >= 0 && yj >= 0) v = h3[(ic * 16 + yi) * 16 + yj];
#pragma unroll
                    for (int oc = 0; oc < 12; oc++)
                        acc[oc] = fmaf(sw4[((oc * 12 + ic) * 3 + di) * 3 + dj],
                                       v, acc[oc]);
                }
            }
        }
#pragma unroll
        for (int oc = 0; oc < 12; oc++)
            h4[(oc * 8 + i) * 8 + j] = leaky(acc[oc]);
    }
    __syncthreads();

    // ---- conv5 : 96 threads, (oc in 0..5, pos in 0..15)
    if (tid < 96) {
        const int oc = tid >> 4;
        const int p  = tid & 15;
        const int i  = p >> 2;
        const int jj = p & 3;
        float acc = sb5[oc];
        for (int ic = 0; ic < 12; ic++) {
#pragma unroll
            for (int di = 0; di < 3; di++) {
#pragma unroll
                for (int dj = 0; dj < 3; dj++) {
                    const int yi = 2 * i + di - 1;     // -1..7
                    const int yj = 2 * jj + dj - 1;    // -1..7
                    float v = 0.f;
                    if (yi >= 0 && yj >= 0) v = h4[(ic * 8 + yi) * 8 + yj];
                    acc = fmaf(sw5[((oc * 12 + ic) * 3 + di) * 3 + dj], v, acc);
                }
            }
        }
        h5[oc * 16 + p] = leaky(acc);
    }
    __syncthreads();

    // ---- conv6 (1x1) + relu -> g_pal : 48 threads
    if (tid < 48) {
        const int c = tid >> 4;
        const int k = tid & 15;
        float acc = sb6[c];
#pragma unroll
        for (int ic = 0; ic < 6; ic++)
            acc = fmaf(sw6[c * 6 + ic], h5[ic * 16 + k], acc);
        g_pal[b * 48 + c * 16 + k] = fmaxf(acc, 0.f);
    }
}

// ---------------------------------------------------------------------------
// gather: per pixel, max over 16 logits, sum palette colors of all classes
// tied at the max (exactly the onehot-sum semantics of the reference; softmax
// is monotone so argmax/ties on logits == argmax/ties on probs up to ~1e-7
// probability rounding corner cases).
// float4-vectorized: thread handles 4 pixels. grid (157, 16), 256 threads.
// ---------------------------------------------------------------------------
__global__ void gather_kernel(const float* __restrict__ logits,
                              float* __restrict__ out) {
    const int b = blockIdx.y;
    const int p = blockIdx.x * blockDim.x + threadIdx.x;   // float4 index in image

    __shared__ float spal[48];
    if (threadIdx.x < 48) spal[threadIdx.x] = g_pal[b * 48 + threadIdx.x];
    __syncthreads();

    if (p >= HW4) return;

    const float4* lg = reinterpret_cast<const float4*>(logits)
                       + (size_t)b * 16 * HW4 + p;

    float4 l[16];
#pragma unroll
    for (int k = 0; k < 16; k++) l[k] = lg[(size_t)k * HW4];

    float4 mx = l[0];
#pragma unroll
    for (int k = 1; k < 16; k++) {
        mx.x = fmaxf(mx.x, l[k].x);
        mx.y = fmaxf(mx.y, l[k].y);
        mx.z = fmaxf(mx.z, l[k].z);
        mx.w = fmaxf(mx.w, l[k].w);
    }

    float4 a0 = make_float4(0.f, 0.f, 0.f, 0.f);
    float4 a1 = a0, a2 = a0;

#pragma unroll
    for (int k = 0; k < 16; k++) {
        const float p0 = spal[k];
        const float p1 = spal[16 + k];
        const float p2 = spal[32 + k];

        const float mxk = (l[k].x == mx.x) ? 1.f : 0.f;
        const float myk = (l[k].y == mx.y) ? 1.f : 0.f;
        const float mzk = (l[k].z == mx.z) ? 1.f : 0.f;
        const float mwk = (l[k].w == mx.w) ? 1.f : 0.f;

        a0.x = fmaf(mxk, p0, a0.x); a0.y = fmaf(myk, p0, a0.y);
        a0.z = fmaf(mzk, p0, a0.z); a0.w = fmaf(mwk, p0, a0.w);
        a1.x = fmaf(mxk, p1, a1.x); a1.y = fmaf(myk, p1, a1.y);
        a1.z = fmaf(mzk, p1, a1.z); a1.w = fmaf(mwk, p1, a1.w);
        a2.x = fmaf(mxk, p2, a2.x); a2.y = fmaf(myk, p2, a2.y);
        a2.z = fmaf(mzk, p2, a2.z); a2.w = fmaf(mwk, p2, a2.w);
    }

    float4* o = reinterpret_cast<float4*>(out) + (size_t)(b * 3) * HW4 + p;
    o[0]           = a0;
    o[HW4]         = a1;
    o[2 * (size_t)HW4] = a2;
}

// ---------------------------------------------------------------------------
extern "C" void kernel_launch(void* const* d_in, const int* in_sizes, int n_in,
                              void* d_out, int out_size) {
    (void)in_sizes; (void)n_in; (void)out_size;
    const float* x  = (const float*)d_in[0];
    const float* bl = (const float*)d_in[1];
    const float* w1 = (const float*)d_in[2];
    const float* b1 = (const float*)d_in[3];
    const float* w2 = (const float*)d_in[4];
    const float* b2 = (const float*)d_in[5];
    const float* w3 = (const float*)d_in[6];
    const float* b3 = (const float*)d_in[7];
    const float* w4 = (const float*)d_in[8];
    const float* b4 = (const float*)d_in[9];
    const float* w5 = (const float*)d_in[10];
    const float* b5 = (const float*)d_in[11];
    const float* w6 = (const float*)d_in[12];
    const float* b6 = (const float*)d_in[13];
    float* out = (float*)d_out;

    conv1_kernel<<<dim3(4, BATCH), 256>>>(x, w1, b1);
    conv2_kernel<<<dim3(4, BATCH), 128>>>(w2, b2);
    conv_tail_kernel<<<BATCH, 256>>>(w3, b3, w4, b4, w5, b5, w6, b6);
    gather_kernel<<<dim3((HW4 + 255) / 256, BATCH), 256>>>(bl, out);
}